// round 4
// baseline (speedup 1.0000x reference)
#include <cuda_runtime.h>
#include <cstdint>

// ================= scratch (static device globals) =================
__device__ __align__(16) float g_xt    [64L*4096*32];   // x transposed [img][p][cin], tf32-rounded
__device__ __align__(16) float g_y0t   [64L*4096*192];  // conv0 out [img][p][cout] (gate|hid|res)
__device__ __align__(16) float g_out0t [64L*4096*64];   // layer0 out [img][p][c] (full precision, residual)
__device__ __align__(16) float g_out0tf[64L*4096*64];   // layer0 out, tf32-rounded (conv1 B input)
__device__ __align__(16) float g_y1t   [64L*4096*128];  // conv1 out [img][p][cout] (gate|hid)
__device__ __align__(16) float g_A0    [2*9*128*32];    // conv0 weights [tile][tap][row128][cin32], tf32
__device__ __align__(16) float g_A1    [18*128*32];     // conv1 weights [chunk][row128][cin32], tf32

// ================= helpers =================
static __device__ __forceinline__ uint32_t s2u(const void* p) {
    uint32_t a;
    asm("{ .reg .u64 t; cvta.to.shared.u64 t, %1; cvt.u32.u64 %0, t; }" : "=r"(a) : "l"(p));
    return a;
}
static __device__ __forceinline__ uint32_t f2tf(float f) {
    uint32_t u;
    asm("cvt.rna.tf32.f32 %0, %1;" : "=r"(u) : "f"(f));
    return u;
}
static __device__ __forceinline__ void cp16(uint32_t daddr, const void* gptr, bool pred) {
    int sz = pred ? 16 : 0;
    asm volatile("cp.async.ca.shared.global [%0], [%1], 16, %2;"
                 :: "r"(daddr), "l"(gptr), "r"(sz));
}
static __device__ __forceinline__ void mma_tf32(float& d0, float& d1, float& d2, float& d3,
                                                uint32_t a0, uint32_t a1, uint32_t a2, uint32_t a3,
                                                uint32_t b0, uint32_t b1) {
    asm volatile("mma.sync.aligned.m16n8k8.row.col.f32.tf32.tf32.f32 "
                 "{%0,%1,%2,%3}, {%4,%5,%6,%7}, {%8,%9}, {%0,%1,%2,%3};"
                 : "+f"(d0), "+f"(d1), "+f"(d2), "+f"(d3)
                 : "r"(a0), "r"(a1), "r"(a2), "r"(a3), "r"(b0), "r"(b1));
}

// ================= pre-processing =================
// x [img][32][4096] -> g_xt [img][p][32]  (tf32-rounded)
__global__ void transpose_x(const float* __restrict__ x) {
    __shared__ float s[32][137];
    const int img = blockIdx.y, p0 = blockIdx.x * 128, t = threadIdx.x;
    const int c8 = t >> 5, pq = t & 31;
    for (int cc = c8; cc < 32; cc += 8) {
        float4 v = *(const float4*)(x + ((size_t)img * 32 + cc) * 4096 + p0 + pq * 4);
        s[cc][pq*4+0] = v.x; s[cc][pq*4+1] = v.y; s[cc][pq*4+2] = v.z; s[cc][pq*4+3] = v.w;
    }
    __syncthreads();
    const int pl = t >> 3, cq = t & 7;
    for (int pp = pl; pp < 128; pp += 32) {
        float4 v;
        v.x = __uint_as_float(f2tf(s[cq*4+0][pp]));
        v.y = __uint_as_float(f2tf(s[cq*4+1][pp]));
        v.z = __uint_as_float(f2tf(s[cq*4+2][pp]));
        v.w = __uint_as_float(f2tf(s[cq*4+3][pp]));
        *(float4*)(g_xt + ((size_t)img * 4096 + p0 + pp) * 32 + cq * 4) = v;
    }
}

// conv0 weights (W0 ++ R0) -> [tile][tap][row][cin], tf32-rounded. tile1 rows >=64 are zero.
__global__ void packA0(const float* __restrict__ W0, const float* __restrict__ R0) {
    int idx = blockIdx.x * 256 + threadIdx.x;      // 73728
    if (idx >= 73728) return;
    int tile = idx / 36864;
    int rem  = idx - tile * 36864;
    int ck   = rem >> 12;            // tap 0..8
    int row  = (rem >> 5) & 127;
    int cin  = rem & 31;
    int cout = tile * 128 + row;
    float v = 0.0f;
    if (cout < 128)      v = W0[cout * 288 + cin * 9 + ck];
    else if (cout < 192) v = R0[(cout - 128) * 288 + cin * 9 + ck];
    g_A0[idx] = __uint_as_float(f2tf(v));
}
__global__ void packA1(const float* __restrict__ W1) {
    int idx = blockIdx.x * 256 + threadIdx.x;      // 73728
    if (idx >= 73728) return;
    int ck  = idx >> 12;             // chunk 0..17 : tap = ck>>1, cin half = ck&1
    int row = (idx >> 5) & 127;
    int cl  = idx & 31;
    int tap = ck >> 1;
    int cin = ((ck & 1) << 5) + cl;
    g_A1[idx] = __uint_as_float(f2tf(W1[row * 576 + cin * 9 + tap]));
}

// ================= tf32 HMMA implicit-GEMM conv =================
// CTA: 128 couts x 256 pixels, K-chunks of 32. 8 warps (2m x 4n), warp 64x64 via m16n8k8.
#define PITCH 36
#define ATILE_BYTES (128*PITCH*4)            // 18432
#define BTILE_BYTES (256*PITCH*4)            // 36864
#define BUF_BYTES   (ATILE_BYTES+BTILE_BYTES) // 55296
#define EPI_PITCH   132
#define SMEM_BYTES  (256*EPI_PITCH*4)        // 135168 (>= 2*BUF_BYTES = 110592)

__global__ __launch_bounds__(256, 1) void conv_tc(int mode, const float* __restrict__ bias) {
    extern __shared__ __align__(16) char smem[];
    const uint32_t sb = s2u(smem);
    const int tid  = threadIdx.x;
    const int lane = tid & 31;
    const int wid  = tid >> 5;
    const int wm   = wid >> 2;       // 0..1
    const int wn   = wid & 3;        // 0..3

    const float* Xt; float* Y; const float* Aw; int C, NCH, CoutS;
    if (mode == 0) { Xt = g_xt;     Y = g_y0t; Aw = g_A0 + blockIdx.y * 36864; C = 32; NCH = 9;  CoutS = 192; }
    else           { Xt = g_out0tf; Y = g_y1t; Aw = g_A1;                      C = 64; NCH = 18; CoutS = 128; }
    const int m0  = blockIdx.y * 128;
    const int img = blockIdx.z;
    const int n0  = blockIdx.x * 256;
    const float* Ximg = Xt + (size_t)img * 4096 * C;

    float acc[4][8][4];
    #pragma unroll
    for (int a = 0; a < 4; a++)
        #pragma unroll
        for (int b = 0; b < 8; b++)
            #pragma unroll
            for (int c = 0; c < 4; c++) acc[a][b][c] = 0.0f;

    // ---- prefetch one K-chunk into buffer buf ----
    const int arow = tid >> 1;             // 0..127
    const int aq0  = (tid & 1) * 4;        // 0 or 4
    auto prefetch = [&](int ck, int buf) {
        const uint32_t abase = sb + buf * BUF_BYTES;
        const uint32_t bbase = abase + ATILE_BYTES;
        const float* asrc = Aw + ck * 4096;
        #pragma unroll
        for (int i = 0; i < 4; i++) {
            int q = aq0 + i;
            cp16(abase + (arow * PITCH + q * 4) * 4, asrc + arow * 32 + q * 4, true);
        }
        const int tap  = (C == 32) ? ck : (ck >> 1);
        const int cin0 = (C == 32) ? 0  : ((ck & 1) << 5);
        const int r = tap / 3 - 1;
        const int s = tap - (tap / 3) * 3 - 1;
        const int d = r * 64 + s;
        const int P = n0 + tid;            // one pixel row per thread
        const int y = P >> 6, x = P & 63;
        const bool ok = ((unsigned)(y + r) < 64u) && ((unsigned)(x + s) < 64u);
        const float* bsrc = Ximg + (long)(P + d) * C + cin0;
        #pragma unroll
        for (int q = 0; q < 8; q++)
            cp16(bbase + (tid * PITCH + q * 4) * 4, bsrc + q * 4, ok);
    };

    prefetch(0, 0);
    asm volatile("cp.async.commit_group;" ::: "memory");

    for (int ck = 0; ck < NCH; ck++) {
        const int buf = ck & 1;
        if (ck + 1 < NCH) prefetch(ck + 1, buf ^ 1);
        asm volatile("cp.async.commit_group;" ::: "memory");
        asm volatile("cp.async.wait_group 1;" ::: "memory");
        __syncthreads();

        const uint32_t* Asu = (const uint32_t*)(smem + buf * BUF_BYTES);
        const uint32_t* Bsu = (const uint32_t*)(smem + buf * BUF_BYTES + ATILE_BYTES);
        const int rb = wm * 64 + (lane >> 2);
        const int ct = lane & 3;
        #pragma unroll
        for (int ks = 0; ks < 4; ks++) {
            const int c = ks * 8 + ct;
            uint32_t afr[4][4];
            #pragma unroll
            for (int mf = 0; mf < 4; mf++) {
                const int base = (rb + mf * 16) * PITCH + c;
                afr[mf][0] = Asu[base];
                afr[mf][1] = Asu[base + 8 * PITCH];
                afr[mf][2] = Asu[base + 4];
                afr[mf][3] = Asu[base + 8 * PITCH + 4];
            }
            uint32_t bfr[8][2];
            #pragma unroll
            for (int nf = 0; nf < 8; nf++) {
                const int nrow = wn * 64 + nf * 8 + (lane >> 2);
                bfr[nf][0] = Bsu[nrow * PITCH + c];
                bfr[nf][1] = Bsu[nrow * PITCH + c + 4];
            }
            #pragma unroll
            for (int nf = 0; nf < 8; nf++)
                #pragma unroll
                for (int mf = 0; mf < 4; mf++)
                    mma_tf32(acc[mf][nf][0], acc[mf][nf][1], acc[mf][nf][2], acc[mf][nf][3],
                             afr[mf][0], afr[mf][1], afr[mf][2], afr[mf][3],
                             bfr[nf][0], bfr[nf][1]);
        }
        __syncthreads();
    }

    // ---- epilogue: acc -> smem[px][cout] -> coalesced global stores ----
    {
        float* sm = (float*)smem;
        #pragma unroll
        for (int mf = 0; mf < 4; mf++) {
            const int r0 = wm * 64 + mf * 16 + (lane >> 2);
            const int c0 = m0 + r0;
            const float bv0 = (c0     < 128) ? bias[c0]     : 0.0f;
            const float bv1 = (c0 + 8 < 128) ? bias[c0 + 8] : 0.0f;
            #pragma unroll
            for (int nf = 0; nf < 8; nf++) {
                const int cc = wn * 64 + nf * 8 + (lane & 3) * 2;
                sm[cc       * EPI_PITCH + r0]     = acc[mf][nf][0] + bv0;
                sm[(cc + 1) * EPI_PITCH + r0]     = acc[mf][nf][1] + bv0;
                sm[cc       * EPI_PITCH + r0 + 8] = acc[mf][nf][2] + bv1;
                sm[(cc + 1) * EPI_PITCH + r0 + 8] = acc[mf][nf][3] + bv1;
            }
        }
        __syncthreads();
        const int mlen = ((CoutS - m0) < 128) ? (CoutS - m0) : 128;  // 128 or 64
        const int mq   = mlen >> 2;                                  // f4 per row: 32 or 16
        float* Yimg = Y + (size_t)img * 4096 * CoutS;
        const int tot = 256 * mq;
        for (int idx = tid; idx < tot; idx += 256) {
            const int px = idx / mq;
            const int j  = idx - px * mq;
            const float4 v = *(const float4*)&sm[px * EPI_PITCH + j * 4];
            *(float4*)&Yimg[(size_t)(n0 + px) * CoutS + m0 + j * 4] = v;
        }
    }
}

// ================= scans =================
static __device__ __forceinline__ float sigm(float x) { return 1.0f / (1.0f + __expf(-x)); }

// layer0: reads y0t [img][p][192], writes out0t (+ tf32 copy) [img][p][64] + h0 to d_out
__global__ void scan0_kernel(float* __restrict__ out) {
    const int g = blockIdx.x * 256 + threadIdx.x;    // 1,048,576
    const int c = g & 63;
    const int p = (g >> 6) & 4095;
    const int b = g >> 18;
    float h = 0.5f;
    #pragma unroll 1
    for (int t = 0; t < 16; t++) {
        const size_t base = ((size_t)(b * 16 + t) * 4096 + p) * 192;
        const float gate = g_y0t[base + c];
        const float hid  = g_y0t[base + 64 + c];
        const float res  = g_y0t[base + 128 + c];
        const float z  = sigm(gate);
        const float a  = sigm(-gate);
        const float gv = (hid >= 0.0f) ? (hid + 0.5f) : sigm(hid);
        h = a * h + z * gv;
        const float o = h + res;
        const size_t oidx = ((size_t)(b * 16 + t) * 4096 + p) * 64 + c;
        g_out0t [oidx] = o;
        g_out0tf[oidx] = __uint_as_float(f2tf(o));
    }
    out[16777216 + ((size_t)b * 64 + c) * 4096 + p] = h;   // h0 [b][c][p]
}

// layer1: reads y1t [img][p][128] + out0t; writes final out [img][c][p] + h1
__global__ void scan1_kernel(float* __restrict__ out) {
    __shared__ __align__(16) float st[64][68];
    const int t  = threadIdx.x;
    const int pb = blockIdx.x;        // 0..63
    const int b  = blockIdx.y;        // 0..3
    const int p0 = pb * 64;
    const int pl = t >> 2, qb = t & 3;
    const int co = t >> 2, pq = t & 3;
    float h[16];
    #pragma unroll
    for (int i = 0; i < 16; i++) h[i] = 0.5f;

    #pragma unroll 1
    for (int ts = 0; ts < 16; ts++) {
        const int img = b * 16 + ts;
        const size_t rb = (size_t)img * 4096 + p0 + pl;
        #pragma unroll
        for (int j = 0; j < 4; j++) {
            const int c0 = qb * 4 + 16 * j;
            const float4 g4 = *(const float4*)(g_y1t   + rb * 128 + c0);
            const float4 d4 = *(const float4*)(g_y1t   + rb * 128 + 64 + c0);
            const float4 i4 = *(const float4*)(g_out0t + rb * 64 + c0);
            const float gv4[4] = {g4.x, g4.y, g4.z, g4.w};
            const float dv4[4] = {d4.x, d4.y, d4.z, d4.w};
            const float iv4[4] = {i4.x, i4.y, i4.z, i4.w};
            #pragma unroll
            for (int e = 0; e < 4; e++) {
                const float z  = sigm(gv4[e]);
                const float a  = sigm(-gv4[e]);
                const float gg = (dv4[e] >= 0.0f) ? (dv4[e] + 0.5f) : sigm(dv4[e]);
                float hh = a * h[j * 4 + e] + z * gg;
                h[j * 4 + e] = hh;
                st[c0 + e][pl] = hh + iv4[e];
            }
        }
        __syncthreads();
        #pragma unroll
        for (int i = 0; i < 4; i++) {
            const float4 v = *(const float4*)&st[co][pq * 16 + 4 * i];
            *(float4*)(out + ((size_t)img * 64 + co) * 4096 + p0 + pq * 16 + 4 * i) = v;
        }
        __syncthreads();
    }
    // h1 via same transpose
    #pragma unroll
    for (int j = 0; j < 4; j++)
        #pragma unroll
        for (int e = 0; e < 4; e++)
            st[qb * 4 + 16 * j + e][pl] = h[j * 4 + e];
    __syncthreads();
    #pragma unroll
    for (int i = 0; i < 4; i++) {
        const float4 v = *(const float4*)&st[co][pq * 16 + 4 * i];
        *(float4*)(out + 17825792 + ((size_t)b * 64 + co) * 4096 + p0 + pq * 16 + 4 * i) = v;
    }
}

// ================= launch =================
extern "C" void kernel_launch(void* const* d_in, const int* in_sizes, int n_in,
                              void* d_out, int out_size) {
    const float* x  = (const float*)d_in[0];
    const float* W0 = (const float*)d_in[1];
    const float* b0 = (const float*)d_in[2];
    const float* R0 = (const float*)d_in[3];
    const float* W1 = (const float*)d_in[4];
    const float* b1 = (const float*)d_in[5];
    float* out = (float*)d_out;

    static int smem_set = 0;
    if (!smem_set) {
        cudaFuncSetAttribute(conv_tc, cudaFuncAttributeMaxDynamicSharedMemorySize, SMEM_BYTES);
        smem_set = 1;
    }

    transpose_x<<<dim3(32, 64), 256>>>(x);
    packA0<<<288, 256>>>(W0, R0);
    packA1<<<288, 256>>>(W1);

    conv_tc<<<dim3(16, 2, 64), 256, SMEM_BYTES>>>(0, b0);
    scan0_kernel<<<4096, 256>>>(out);
    conv_tc<<<dim3(16, 1, 64), 256, SMEM_BYTES>>>(1, b1);
    scan1_kernel<<<dim3(64, 4), 256>>>(out);
}

// round 5
// speedup vs baseline: 1.0003x; 1.0003x over previous
#include <cuda_runtime.h>
#include <cstdint>

// ================= scratch (static device globals) =================
__device__ __align__(16) float g_xt    [64L*4096*32];   // x transposed [img][p][cin], tf32-rounded
__device__ __align__(16) float g_y0t   [64L*4096*192];  // conv0 out [img][p][cout] (gate|hid|res)
__device__ __align__(16) float g_out0t [64L*4096*64];   // layer0 out [img][p][c] (full precision, residual)
__device__ __align__(16) float g_out0tf[64L*4096*64];   // layer0 out, tf32-rounded (conv1 B input)
__device__ __align__(16) float g_y1t   [64L*4096*128];  // conv1 out [img][p][cout] (gate|hid)
__device__ __align__(16) float g_A0    [2*9*128*32];    // conv0 weights [tile][tap][row128][cin32], tf32
__device__ __align__(16) float g_A1    [18*128*32];     // conv1 weights [chunk][row128][cin32], tf32

// ================= helpers =================
static __device__ __forceinline__ uint32_t s2u(const void* p) {
    uint32_t a;
    asm("{ .reg .u64 t; cvta.to.shared.u64 t, %1; cvt.u32.u64 %0, t; }" : "=r"(a) : "l"(p));
    return a;
}
static __device__ __forceinline__ uint32_t f2tf(float f) {
    uint32_t u;
    asm("cvt.rna.tf32.f32 %0, %1;" : "=r"(u) : "f"(f));
    return u;
}
static __device__ __forceinline__ void cp16(uint32_t daddr, const void* gptr, bool pred) {
    int sz = pred ? 16 : 0;
    asm volatile("cp.async.ca.shared.global [%0], [%1], 16, %2;"
                 :: "r"(daddr), "l"(gptr), "r"(sz));
}
static __device__ __forceinline__ void mma_tf32(float& d0, float& d1, float& d2, float& d3,
                                                uint32_t a0, uint32_t a1, uint32_t a2, uint32_t a3,
                                                uint32_t b0, uint32_t b1) {
    asm volatile("mma.sync.aligned.m16n8k8.row.col.f32.tf32.tf32.f32 "
                 "{%0,%1,%2,%3}, {%4,%5,%6,%7}, {%8,%9}, {%0,%1,%2,%3};"
                 : "+f"(d0), "+f"(d1), "+f"(d2), "+f"(d3)
                 : "r"(a0), "r"(a1), "r"(a2), "r"(a3), "r"(b0), "r"(b1));
}

// ================= pre-processing =================
// x [img][32][4096] -> g_xt [img][p][32]  (tf32-rounded)
__global__ void transpose_x(const float* __restrict__ x) {
    __shared__ float s[32][137];
    const int img = blockIdx.y, p0 = blockIdx.x * 128, t = threadIdx.x;
    const int c8 = t >> 5, pq = t & 31;
    for (int cc = c8; cc < 32; cc += 8) {
        float4 v = *(const float4*)(x + ((size_t)img * 32 + cc) * 4096 + p0 + pq * 4);
        s[cc][pq*4+0] = v.x; s[cc][pq*4+1] = v.y; s[cc][pq*4+2] = v.z; s[cc][pq*4+3] = v.w;
    }
    __syncthreads();
    const int pl = t >> 3, cq = t & 7;
    for (int pp = pl; pp < 128; pp += 32) {
        float4 v;
        v.x = __uint_as_float(f2tf(s[cq*4+0][pp]));
        v.y = __uint_as_float(f2tf(s[cq*4+1][pp]));
        v.z = __uint_as_float(f2tf(s[cq*4+2][pp]));
        v.w = __uint_as_float(f2tf(s[cq*4+3][pp]));
        *(float4*)(g_xt + ((size_t)img * 4096 + p0 + pp) * 32 + cq * 4) = v;
    }
}

// conv0 weights (W0 ++ R0) -> [tile][tap][row][cin], tf32-rounded. tile1 rows >=64 are zero.
__global__ void packA0(const float* __restrict__ W0, const float* __restrict__ R0) {
    int idx = blockIdx.x * 256 + threadIdx.x;      // 73728
    if (idx >= 73728) return;
    int tile = idx / 36864;
    int rem  = idx - tile * 36864;
    int ck   = rem >> 12;            // tap 0..8
    int row  = (rem >> 5) & 127;
    int cin  = rem & 31;
    int cout = tile * 128 + row;
    float v = 0.0f;
    if (cout < 128)      v = W0[cout * 288 + cin * 9 + ck];
    else if (cout < 192) v = R0[(cout - 128) * 288 + cin * 9 + ck];
    g_A0[idx] = __uint_as_float(f2tf(v));
}
__global__ void packA1(const float* __restrict__ W1) {
    int idx = blockIdx.x * 256 + threadIdx.x;      // 73728
    if (idx >= 73728) return;
    int ck  = idx >> 12;             // chunk 0..17 : tap = ck>>1, cin half = ck&1
    int row = (idx >> 5) & 127;
    int cl  = idx & 31;
    int tap = ck >> 1;
    int cin = ((ck & 1) << 5) + cl;
    g_A1[idx] = __uint_as_float(f2tf(W1[row * 576 + cin * 9 + tap]));
}

// ================= tf32 HMMA implicit-GEMM conv =================
// CTA: 128 couts x 256 pixels, K-chunks of 32. 8 warps (2m x 4n), warp 64x64 via m16n8k8.
#define PITCH 36
#define ATILE_BYTES (128*PITCH*4)            // 18432
#define BTILE_BYTES (256*PITCH*4)            // 36864
#define BUF_BYTES   (ATILE_BYTES+BTILE_BYTES) // 55296
#define EPI_PITCH   132
#define SMEM_BYTES  (256*EPI_PITCH*4)        // 135168 (>= 2*BUF_BYTES = 110592)

__global__ __launch_bounds__(256, 1) void conv_tc(int mode, const float* __restrict__ bias) {
    extern __shared__ __align__(16) char smem[];
    const uint32_t sb = s2u(smem);
    const int tid  = threadIdx.x;
    const int lane = tid & 31;
    const int wid  = tid >> 5;
    const int wm   = wid >> 2;       // 0..1
    const int wn   = wid & 3;        // 0..3

    const float* Xt; float* Y; const float* Aw; int C, NCH, CoutS;
    if (mode == 0) { Xt = g_xt;     Y = g_y0t; Aw = g_A0 + blockIdx.y * 36864; C = 32; NCH = 9;  CoutS = 192; }
    else           { Xt = g_out0tf; Y = g_y1t; Aw = g_A1;                      C = 64; NCH = 18; CoutS = 128; }
    const int m0  = blockIdx.y * 128;
    const int img = blockIdx.z;
    const int n0  = blockIdx.x * 256;
    const float* Ximg = Xt + (size_t)img * 4096 * C;

    float acc[4][8][4];
    #pragma unroll
    for (int a = 0; a < 4; a++)
        #pragma unroll
        for (int b = 0; b < 8; b++)
            #pragma unroll
            for (int c = 0; c < 4; c++) acc[a][b][c] = 0.0f;

    // ---- prefetch one K-chunk into buffer buf ----
    const int arow = tid >> 1;             // 0..127
    const int aq0  = (tid & 1) * 4;        // 0 or 4
    auto prefetch = [&](int ck, int buf) {
        const uint32_t abase = sb + buf * BUF_BYTES;
        const uint32_t bbase = abase + ATILE_BYTES;
        const float* asrc = Aw + ck * 4096;
        #pragma unroll
        for (int i = 0; i < 4; i++) {
            int q = aq0 + i;
            cp16(abase + (arow * PITCH + q * 4) * 4, asrc + arow * 32 + q * 4, true);
        }
        const int tap  = (C == 32) ? ck : (ck >> 1);
        const int cin0 = (C == 32) ? 0  : ((ck & 1) << 5);
        const int r = tap / 3 - 1;
        const int s = tap - (tap / 3) * 3 - 1;
        const int d = r * 64 + s;
        const int P = n0 + tid;            // one pixel row per thread
        const int y = P >> 6, x = P & 63;
        const bool ok = ((unsigned)(y + r) < 64u) && ((unsigned)(x + s) < 64u);
        const float* bsrc = Ximg + (long)(P + d) * C + cin0;
        #pragma unroll
        for (int q = 0; q < 8; q++)
            cp16(bbase + (tid * PITCH + q * 4) * 4, bsrc + q * 4, ok);
    };

    prefetch(0, 0);
    asm volatile("cp.async.commit_group;" ::: "memory");

    for (int ck = 0; ck < NCH; ck++) {
        const int buf = ck & 1;
        if (ck + 1 < NCH) prefetch(ck + 1, buf ^ 1);
        asm volatile("cp.async.commit_group;" ::: "memory");
        asm volatile("cp.async.wait_group 1;" ::: "memory");
        __syncthreads();

        const uint32_t* Asu = (const uint32_t*)(smem + buf * BUF_BYTES);
        const uint32_t* Bsu = (const uint32_t*)(smem + buf * BUF_BYTES + ATILE_BYTES);
        const int rb = wm * 64 + (lane >> 2);
        const int ct = lane & 3;
        #pragma unroll
        for (int ks = 0; ks < 4; ks++) {
            const int c = ks * 8 + ct;
            uint32_t afr[4][4];
            #pragma unroll
            for (int mf = 0; mf < 4; mf++) {
                const int base = (rb + mf * 16) * PITCH + c;
                afr[mf][0] = Asu[base];
                afr[mf][1] = Asu[base + 8 * PITCH];
                afr[mf][2] = Asu[base + 4];
                afr[mf][3] = Asu[base + 8 * PITCH + 4];
            }
            uint32_t bfr[8][2];
            #pragma unroll
            for (int nf = 0; nf < 8; nf++) {
                const int nrow = wn * 64 + nf * 8 + (lane >> 2);
                bfr[nf][0] = Bsu[nrow * PITCH + c];
                bfr[nf][1] = Bsu[nrow * PITCH + c + 4];
            }
            #pragma unroll
            for (int nf = 0; nf < 8; nf++)
                #pragma unroll
                for (int mf = 0; mf < 4; mf++)
                    mma_tf32(acc[mf][nf][0], acc[mf][nf][1], acc[mf][nf][2], acc[mf][nf][3],
                             afr[mf][0], afr[mf][1], afr[mf][2], afr[mf][3],
                             bfr[nf][0], bfr[nf][1]);
        }
        __syncthreads();
    }

    // ---- epilogue: acc -> smem[px][cout] -> coalesced global stores ----
    {
        float* sm = (float*)smem;
        #pragma unroll
        for (int mf = 0; mf < 4; mf++) {
            const int r0 = wm * 64 + mf * 16 + (lane >> 2);
            const int c0 = m0 + r0;
            const float bv0 = (c0     < 128) ? bias[c0]     : 0.0f;
            const float bv1 = (c0 + 8 < 128) ? bias[c0 + 8] : 0.0f;
            #pragma unroll
            for (int nf = 0; nf < 8; nf++) {
                const int cc = wn * 64 + nf * 8 + (lane & 3) * 2;
                sm[cc       * EPI_PITCH + r0]     = acc[mf][nf][0] + bv0;
                sm[(cc + 1) * EPI_PITCH + r0]     = acc[mf][nf][1] + bv0;
                sm[cc       * EPI_PITCH + r0 + 8] = acc[mf][nf][2] + bv1;
                sm[(cc + 1) * EPI_PITCH + r0 + 8] = acc[mf][nf][3] + bv1;
            }
        }
        __syncthreads();
        const int mlen = ((CoutS - m0) < 128) ? (CoutS - m0) : 128;  // 128 or 64
        const int mq   = mlen >> 2;                                  // f4 per row: 32 or 16
        float* Yimg = Y + (size_t)img * 4096 * CoutS;
        const int tot = 256 * mq;
        for (int idx = tid; idx < tot; idx += 256) {
            const int px = idx / mq;
            const int j  = idx - px * mq;
            const float4 v = *(const float4*)&sm[px * EPI_PITCH + j * 4];
            *(float4*)&Yimg[(size_t)(n0 + px) * CoutS + m0 + j * 4] = v;
        }
    }
}

// ================= scans =================
static __device__ __forceinline__ float sigm(float x) { return 1.0f / (1.0f + __expf(-x)); }

// layer0: reads y0t [img][p][192], writes out0t (+ tf32 copy) [img][p][64] + h0 to d_out
__global__ void scan0_kernel(float* __restrict__ out) {
    const int g = blockIdx.x * 256 + threadIdx.x;    // 1,048,576
    const int c = g & 63;
    const int p = (g >> 6) & 4095;
    const int b = g >> 18;
    float h = 0.5f;
    #pragma unroll 1
    for (int t = 0; t < 16; t++) {
        const size_t base = ((size_t)(b * 16 + t) * 4096 + p) * 192;
        const float gate = g_y0t[base + c];
        const float hid  = g_y0t[base + 64 + c];
        const float res  = g_y0t[base + 128 + c];
        const float z  = sigm(gate);
        const float a  = sigm(-gate);
        const float gv = (hid >= 0.0f) ? (hid + 0.5f) : sigm(hid);
        h = a * h + z * gv;
        const float o = h + res;
        const size_t oidx = ((size_t)(b * 16 + t) * 4096 + p) * 64 + c;
        g_out0t [oidx] = o;
        g_out0tf[oidx] = __uint_as_float(f2tf(o));
    }
    out[16777216 + ((size_t)b * 64 + c) * 4096 + p] = h;   // h0 [b][c][p]
}

// layer1: reads y1t [img][p][128] + out0t; writes final out [img][c][p] + h1
__global__ void scan1_kernel(float* __restrict__ out) {
    __shared__ __align__(16) float st[64][68];
    const int t  = threadIdx.x;
    const int pb = blockIdx.x;        // 0..63
    const int b  = blockIdx.y;        // 0..3
    const int p0 = pb * 64;
    const int pl = t >> 2, qb = t & 3;
    const int co = t >> 2, pq = t & 3;
    float h[16];
    #pragma unroll
    for (int i = 0; i < 16; i++) h[i] = 0.5f;

    #pragma unroll 1
    for (int ts = 0; ts < 16; ts++) {
        const int img = b * 16 + ts;
        const size_t rb = (size_t)img * 4096 + p0 + pl;
        #pragma unroll
        for (int j = 0; j < 4; j++) {
            const int c0 = qb * 4 + 16 * j;
            const float4 g4 = *(const float4*)(g_y1t   + rb * 128 + c0);
            const float4 d4 = *(const float4*)(g_y1t   + rb * 128 + 64 + c0);
            const float4 i4 = *(const float4*)(g_out0t + rb * 64 + c0);
            const float gv4[4] = {g4.x, g4.y, g4.z, g4.w};
            const float dv4[4] = {d4.x, d4.y, d4.z, d4.w};
            const float iv4[4] = {i4.x, i4.y, i4.z, i4.w};
            #pragma unroll
            for (int e = 0; e < 4; e++) {
                const float z  = sigm(gv4[e]);
                const float a  = sigm(-gv4[e]);
                const float gg = (dv4[e] >= 0.0f) ? (dv4[e] + 0.5f) : sigm(dv4[e]);
                float hh = a * h[j * 4 + e] + z * gg;
                h[j * 4 + e] = hh;
                st[c0 + e][pl] = hh + iv4[e];
            }
        }
        __syncthreads();
        #pragma unroll
        for (int i = 0; i < 4; i++) {
            const float4 v = *(const float4*)&st[co][pq * 16 + 4 * i];
            *(float4*)(out + ((size_t)img * 64 + co) * 4096 + p0 + pq * 16 + 4 * i) = v;
        }
        __syncthreads();
    }
    // h1 via same transpose
    #pragma unroll
    for (int j = 0; j < 4; j++)
        #pragma unroll
        for (int e = 0; e < 4; e++)
            st[qb * 4 + 16 * j + e][pl] = h[j * 4 + e];
    __syncthreads();
    #pragma unroll
    for (int i = 0; i < 4; i++) {
        const float4 v = *(const float4*)&st[co][pq * 16 + 4 * i];
        *(float4*)(out + 17825792 + ((size_t)b * 64 + co) * 4096 + p0 + pq * 16 + 4 * i) = v;
    }
}

// ================= launch =================
extern "C" void kernel_launch(void* const* d_in, const int* in_sizes, int n_in,
                              void* d_out, int out_size) {
    const float* x  = (const float*)d_in[0];
    const float* W0 = (const float*)d_in[1];
    const float* b0 = (const float*)d_in[2];
    const float* R0 = (const float*)d_in[3];
    const float* W1 = (const float*)d_in[4];
    const float* b1 = (const float*)d_in[5];
    float* out = (float*)d_out;

    static int smem_set = 0;
    if (!smem_set) {
        cudaFuncSetAttribute(conv_tc, cudaFuncAttributeMaxDynamicSharedMemorySize, SMEM_BYTES);
        smem_set = 1;
    }

    transpose_x<<<dim3(32, 64), 256>>>(x);
    packA0<<<288, 256>>>(W0, R0);
    packA1<<<288, 256>>>(W1);

    conv_tc<<<dim3(16, 2, 64), 256, SMEM_BYTES>>>(0, b0);
    scan0_kernel<<<4096, 256>>>(out);
    conv_tc<<<dim3(16, 1, 64), 256, SMEM_BYTES>>>(1, b1);
    scan1_kernel<<<dim3(64, 4), 256>>>(out);
}

// round 8
// speedup vs baseline: 1.0853x; 1.0850x over previous
#include <cuda_runtime.h>
#include <cstdint>

// ================= scratch (static device globals) =================
__device__ __align__(16) float g_xt    [64L*4096*32];   // x [img][p][cin], tf32-rounded
__device__ __align__(16) float g_y0t   [64L*4096*192];  // conv0 out [img][p][cout] (gate|hid|res)
__device__ __align__(16) float g_out0t [64L*4096*64];   // layer0 out [img][p][c] (full precision, residual)
__device__ __align__(16) float g_out0tf[64L*4096*64];   // layer0 out, tf32-rounded (conv1 B input)
__device__ __align__(16) float g_y1t   [64L*4096*128];  // conv1 out [img][p][cout] (gate|hid)
__device__ __align__(16) float g_A0    [2*9*128*32];    // conv0 weights [tile][tap][row128][cin32], tf32
__device__ __align__(16) float g_A1    [18*128*32];     // conv1 weights [chunk][row128][cin32], tf32

// ================= helpers =================
static __device__ __forceinline__ uint32_t s2u(const void* p) {
    uint32_t a;
    asm("{ .reg .u64 t; cvta.to.shared.u64 t, %1; cvt.u32.u64 %0, t; }" : "=r"(a) : "l"(p));
    return a;
}
static __device__ __forceinline__ uint32_t f2tf(float f) {
    uint32_t u;
    asm("cvt.rna.tf32.f32 %0, %1;" : "=r"(u) : "f"(f));
    return u;
}
static __device__ __forceinline__ void cp16(uint32_t daddr, const void* gptr, bool pred) {
    int sz = pred ? 16 : 0;
    asm volatile("cp.async.ca.shared.global [%0], [%1], 16, %2;"
                 :: "r"(daddr), "l"(gptr), "r"(sz));
}
static __device__ __forceinline__ void mma_tf32(float& d0, float& d1, float& d2, float& d3,
                                                uint32_t a0, uint32_t a1, uint32_t a2, uint32_t a3,
                                                uint32_t b0, uint32_t b1) {
    asm volatile("mma.sync.aligned.m16n8k8.row.col.f32.tf32.tf32.f32 "
                 "{%0,%1,%2,%3}, {%4,%5,%6,%7}, {%8,%9}, {%0,%1,%2,%3};"
                 : "+f"(d0), "+f"(d1), "+f"(d2), "+f"(d3)
                 : "r"(a0), "r"(a1), "r"(a2), "r"(a3), "r"(b0), "r"(b1));
}

// ================= pre-processing =================
// x [img][32][4096] -> g_xt [img][p][cin]  (tf32-rounded)
__global__ void transpose_x(const float* __restrict__ x) {
    __shared__ float s[32][137];
    const int img = blockIdx.y, p0 = blockIdx.x * 128, t = threadIdx.x;
    const int c8 = t >> 5, pq = t & 31;
    for (int cc = c8; cc < 32; cc += 8) {
        float4 v = *(const float4*)(x + ((size_t)img * 32 + cc) * 4096 + p0 + pq * 4);
        s[cc][pq*4+0] = v.x; s[cc][pq*4+1] = v.y; s[cc][pq*4+2] = v.z; s[cc][pq*4+3] = v.w;
    }
    __syncthreads();
    const int pl = t >> 3, cq = t & 7;
    for (int pp = pl; pp < 128; pp += 32) {
        float4 v;
        v.x = __uint_as_float(f2tf(s[cq*4+0][pp]));
        v.y = __uint_as_float(f2tf(s[cq*4+1][pp]));
        v.z = __uint_as_float(f2tf(s[cq*4+2][pp]));
        v.w = __uint_as_float(f2tf(s[cq*4+3][pp]));
        *(float4*)(g_xt + ((size_t)img * 4096 + p0 + pp) * 32 + cq * 4) = v;
    }
}

// conv0 weights (W0 ++ R0) -> [tile][tap][row][cin], tf32-rounded. tile1 rows >=64 are zero.
__global__ void packA0(const float* __restrict__ W0, const float* __restrict__ R0) {
    int idx = blockIdx.x * 256 + threadIdx.x;      // 73728
    if (idx >= 73728) return;
    int tile = idx / 36864;
    int rem  = idx - tile * 36864;
    int ck   = rem >> 12;            // tap 0..8
    int row  = (rem >> 5) & 127;
    int cin  = rem & 31;
    int cout = tile * 128 + row;
    float v = 0.0f;
    if (cout < 128)      v = W0[cout * 288 + cin * 9 + ck];
    else if (cout < 192) v = R0[(cout - 128) * 288 + cin * 9 + ck];
    g_A0[idx] = __uint_as_float(f2tf(v));
}
__global__ void packA1(const float* __restrict__ W1) {
    int idx = blockIdx.x * 256 + threadIdx.x;      // 73728
    if (idx >= 73728) return;
    int ck  = idx >> 12;             // chunk 0..17 : tap = ck>>1, cin half = ck&1
    int row = (idx >> 5) & 127;
    int cl  = idx & 31;
    int tap = ck >> 1;
    int cin = ((ck & 1) << 5) + cl;
    g_A1[idx] = __uint_as_float(f2tf(W1[row * 576 + cin * 9 + tap]));
}

// ================= tf32 HMMA implicit-GEMM conv =================
// CTA: 128 couts x 128 pixels, K-chunks of 32. 8 warps (2m x 4n), warp 64x32 via m16n8k8.
#define PITCH 36
#define ATILE_BYTES (128*PITCH*4)     // 18432
#define BUF_BYTES   (2*ATILE_BYTES)   // 36864 (A + B)
#define SMEM_BYTES  (2*BUF_BYTES)     // 73728
#define EPIP 132                       // epilogue transpose pitch (floats)

__global__ __launch_bounds__(256) void conv_tc(int mode, const float* __restrict__ bias) {
    extern __shared__ __align__(16) char smem[];
    const uint32_t sb = s2u(smem);
    const int tid  = threadIdx.x;
    const int lane = tid & 31;
    const int wid  = tid >> 5;
    const int wm   = wid >> 2;       // 0..1
    const int wn   = wid & 3;        // 0..3

    const float* Xt; float* Y; const float* Aw; int C, NCH, CoutS;
    if (mode == 0) { Xt = g_xt;     Y = g_y0t; Aw = g_A0 + blockIdx.y * 36864; C = 32; NCH = 9;  CoutS = 192; }
    else           { Xt = g_out0tf; Y = g_y1t; Aw = g_A1;                      C = 64; NCH = 18; CoutS = 128; }
    const int m0  = blockIdx.y * 128;
    const int img = blockIdx.z;
    const int n0  = blockIdx.x * 128;
    const float* Ximg = Xt + (size_t)img * 4096 * C;

    const int lrow = tid >> 1;            // 0..127 (row / pixel)
    const int lq   = (tid & 1) * 2;       // starting q (0 or 2)

    float acc[4][4][4];
    #pragma unroll
    for (int a = 0; a < 4; a++)
        #pragma unroll
        for (int b = 0; b < 4; b++)
            #pragma unroll
            for (int c = 0; c < 4; c++) acc[a][b][c] = 0.0f;

    auto prefetch = [&](int ck, int buf) {
        const uint32_t abase = sb + buf * BUF_BYTES;
        const uint32_t bbase = abase + ATILE_BYTES;
        const float* asrc = Aw + ck * 4096;
        #pragma unroll
        for (int i = 0; i < 2; i++) {
            int q = lq + i;
            cp16(abase + (lrow * PITCH + q * 4) * 4, asrc + lrow * 32 + q * 4, true);
            int q2 = q + 4;
            cp16(abase + (lrow * PITCH + q2 * 4) * 4, asrc + lrow * 32 + q2 * 4, true);
        }
        const int tap  = (C == 32) ? ck : (ck >> 1);
        const int cin0 = (C == 32) ? 0  : ((ck & 1) << 5);
        const int r = tap / 3 - 1;
        const int s = tap - (tap / 3) * 3 - 1;
        const int d = r * 64 + s;
        const int P = n0 + lrow;
        const int y = P >> 6, x = P & 63;
        const bool ok = ((unsigned)(y + r) < 64u) && ((unsigned)(x + s) < 64u);
        const float* bsrc = Ximg + (long)(P + d) * C + cin0;
        #pragma unroll
        for (int i = 0; i < 2; i++) {
            int q = lq + i;
            cp16(bbase + (lrow * PITCH + q * 4) * 4, bsrc + q * 4, ok);
            int q2 = q + 4;
            cp16(bbase + (lrow * PITCH + q2 * 4) * 4, bsrc + q2 * 4, ok);
        }
    };

    prefetch(0, 0);
    asm volatile("cp.async.commit_group;" ::: "memory");

    for (int ck = 0; ck < NCH; ck++) {
        const int buf = ck & 1;
        if (ck + 1 < NCH) prefetch(ck + 1, buf ^ 1);
        asm volatile("cp.async.commit_group;" ::: "memory");
        asm volatile("cp.async.wait_group 1;" ::: "memory");
        __syncthreads();

        const uint32_t* Asu = (const uint32_t*)(smem + buf * BUF_BYTES);
        const uint32_t* Bsu = (const uint32_t*)(smem + buf * BUF_BYTES + ATILE_BYTES);
        const int rb = wm * 64 + (lane >> 2);
        const int ct = lane & 3;
        #pragma unroll
        for (int ks = 0; ks < 4; ks++) {
            const int c = ks * 8 + ct;
            uint32_t afr[4][4];
            #pragma unroll
            for (int mf = 0; mf < 4; mf++) {
                const int base = (rb + mf * 16) * PITCH + c;
                afr[mf][0] = Asu[base];
                afr[mf][1] = Asu[base + 8 * PITCH];
                afr[mf][2] = Asu[base + 4];
                afr[mf][3] = Asu[base + 8 * PITCH + 4];
            }
            uint32_t bfr[4][2];
            #pragma unroll
            for (int nf = 0; nf < 4; nf++) {
                const int nrow = wn * 32 + nf * 8 + (lane >> 2);
                bfr[nf][0] = Bsu[nrow * PITCH + c];
                bfr[nf][1] = Bsu[nrow * PITCH + c + 4];
            }
            #pragma unroll
            for (int nf = 0; nf < 4; nf++)
                #pragma unroll
                for (int mf = 0; mf < 4; mf++)
                    mma_tf32(acc[mf][nf][0], acc[mf][nf][1], acc[mf][nf][2], acc[mf][nf][3],
                             afr[mf][0], afr[mf][1], afr[mf][2], afr[mf][3],
                             bfr[nf][0], bfr[nf][1]);
        }
        __syncthreads();
    }

    // ---- epilogue: acc -> smem[px][cout] -> coalesced global stores ----
    {
        float* sm = (float*)smem;
        #pragma unroll
        for (int mf = 0; mf < 4; mf++) {
            const int r0 = wm * 64 + mf * 16 + (lane >> 2);
            const int c0 = m0 + r0;
            const float bv0 = (c0     < 128) ? bias[c0]     : 0.0f;
            const float bv1 = (c0 + 8 < 128) ? bias[c0 + 8] : 0.0f;
            #pragma unroll
            for (int nf = 0; nf < 4; nf++) {
                const int cc = wn * 32 + nf * 8 + (lane & 3) * 2;
                sm[cc       * EPIP + r0]     = acc[mf][nf][0] + bv0;
                sm[(cc + 1) * EPIP + r0]     = acc[mf][nf][1] + bv0;
                sm[cc       * EPIP + r0 + 8] = acc[mf][nf][2] + bv1;
                sm[(cc + 1) * EPIP + r0 + 8] = acc[mf][nf][3] + bv1;
            }
        }
        __syncthreads();
        const int mlen = ((CoutS - m0) < 128) ? (CoutS - m0) : 128;  // 128 or 64
        const int mq   = mlen >> 2;                                  // f4 per row: 32 or 16
        float* Yimg = Y + (size_t)img * 4096 * CoutS;
        const int tot = 128 * mq;
        for (int idx = tid; idx < tot; idx += 256) {
            const int px = idx / mq;
            const int j  = idx - px * mq;
            const float4 v = *(const float4*)&sm[px * EPIP + j * 4];
            *(float4*)&Yimg[(size_t)(n0 + px) * CoutS + m0 + j * 4] = v;
        }
    }
}

// ================= scans =================
static __device__ __forceinline__ float sigm(float x) { return 1.0f / (1.0f + __expf(-x)); }

// layer0: reads y0t [img][p][192], writes out0t (+ tf32 copy) [img][p][64] + h0
__global__ void scan0_kernel(float* __restrict__ out) {
    const int g = blockIdx.x * 256 + threadIdx.x;    // 1,048,576
    const int c = g & 63;
    const int p = (g >> 6) & 4095;
    const int b = g >> 18;
    float h = 0.5f;
    #pragma unroll 1
    for (int t = 0; t < 16; t++) {
        const size_t base = ((size_t)(b * 16 + t) * 4096 + p) * 192;
        const float gate = g_y0t[base + c];
        const float hid  = g_y0t[base + 64 + c];
        const float res  = g_y0t[base + 128 + c];
        const float z  = sigm(gate);
        const float a  = sigm(-gate);
        const float gv = (hid >= 0.0f) ? (hid + 0.5f) : sigm(hid);
        h = a * h + z * gv;
        const float o = h + res;
        const size_t oidx = ((size_t)(b * 16 + t) * 4096 + p) * 64 + c;
        g_out0t [oidx] = o;
        g_out0tf[oidx] = __uint_as_float(f2tf(o));
    }
    out[16777216 + ((size_t)b * 64 + c) * 4096 + p] = h;   // h0 [b][c][p]
}

// layer1: reads y1t [img][p][128] + out0t; writes final out [img][c][p] + h1
__global__ void scan1_kernel(float* __restrict__ out) {
    __shared__ __align__(16) float st[64][68];
    const int t  = threadIdx.x;
    const int pb = blockIdx.x;        // 0..63
    const int b  = blockIdx.y;        // 0..3
    const int p0 = pb * 64;
    const int pl = t >> 2, qb = t & 3;
    const int co = t >> 2, pq = t & 3;
    float h[16];
    #pragma unroll
    for (int i = 0; i < 16; i++) h[i] = 0.5f;

    #pragma unroll 1
    for (int ts = 0; ts < 16; ts++) {
        const int img = b * 16 + ts;
        const size_t rb = (size_t)img * 4096 + p0 + pl;
        #pragma unroll
        for (int j = 0; j < 4; j++) {
            const int c0 = qb * 4 + 16 * j;
            const float4 g4 = *(const float4*)(g_y1t   + rb * 128 + c0);
            const float4 d4 = *(const float4*)(g_y1t   + rb * 128 + 64 + c0);
            const float4 i4 = *(const float4*)(g_out0t + rb * 64 + c0);
            const float gv4[4] = {g4.x, g4.y, g4.z, g4.w};
            const float dv4[4] = {d4.x, d4.y, d4.z, d4.w};
            const float iv4[4] = {i4.x, i4.y, i4.z, i4.w};
            #pragma unroll
            for (int e = 0; e < 4; e++) {
                const float z  = sigm(gv4[e]);
                const float a  = sigm(-gv4[e]);
                const float gg = (dv4[e] >= 0.0f) ? (dv4[e] + 0.5f) : sigm(dv4[e]);
                float hh = a * h[j * 4 + e] + z * gg;
                h[j * 4 + e] = hh;
                st[c0 + e][pl] = hh + iv4[e];
            }
        }
        __syncthreads();
        #pragma unroll
        for (int i = 0; i < 4; i++) {
            const float4 v = *(const float4*)&st[co][pq * 16 + 4 * i];
            *(float4*)(out + ((size_t)img * 64 + co) * 4096 + p0 + pq * 16 + 4 * i) = v;
        }
        __syncthreads();
    }
    #pragma unroll
    for (int j = 0; j < 4; j++)
        #pragma unroll
        for (int e = 0; e < 4; e++)
            st[qb * 4 + 16 * j + e][pl] = h[j * 4 + e];
    __syncthreads();
    #pragma unroll
    for (int i = 0; i < 4; i++) {
        const float4 v = *(const float4*)&st[co][pq * 16 + 4 * i];
        *(float4*)(out + 17825792 + ((size_t)b * 64 + co) * 4096 + p0 + pq * 16 + 4 * i) = v;
    }
}

// ================= launch =================
extern "C" void kernel_launch(void* const* d_in, const int* in_sizes, int n_in,
                              void* d_out, int out_size) {
    const float* x  = (const float*)d_in[0];
    const float* W0 = (const float*)d_in[1];
    const float* b0 = (const float*)d_in[2];
    const float* R0 = (const float*)d_in[3];
    const float* W1 = (const float*)d_in[4];
    const float* b1 = (const float*)d_in[5];
    float* out = (float*)d_out;

    cudaFuncSetAttribute(conv_tc, cudaFuncAttributeMaxDynamicSharedMemorySize, SMEM_BYTES);

    transpose_x<<<dim3(32, 64), 256>>>(x);
    packA0<<<288, 256>>>(W0, R0);
    packA1<<<288, 256>>>(W1);

    conv_tc<<<dim3(32, 2, 64), 256, SMEM_BYTES>>>(0, b0);
    scan0_kernel<<<4096, 256>>>(out);
    conv_tc<<<dim3(32, 1, 64), 256, SMEM_BYTES>>>(1, b1);
    scan1_kernel<<<dim3(64, 4), 256>>>(out);
}